// round 2
// baseline (speedup 1.0000x reference)
#include <cuda_runtime.h>
#include <cstdint>

// Problem constants (fixed by the reference)
#define BB 16
#define NN 8192
#define MM 2048
#define KK 32
#define CC 128
#define GROUPS 2            // (b,m) groups per CTA -> one 32KB bulk store
#define ROWS (GROUPS * KK)  // 64 feature rows per CTA

// out layout: [pts (B*M*K*3 floats)] ++ [features (B*M*K*C floats)]
//
// One CTA per GROUPS consecutive (b,m). 256 threads = 8 warps.
//  - all 8 warps gather feature rows into SMEM (LDG.128 -> STS.128),
//    8 rows per warp, fully coalesced 512B per row.
//  - warps 0..GROUPS-1 additionally compute the normalized relative coords
//    for their group (lane = k) and write them directly (tiny, 96B/group).
//  - after __syncthreads, one thread issues a single cp.async.bulk
//    SMEM -> GMEM store of the CTA's entire contiguous feature output
//    (GROUPS*KK*CC floats = 32KB), bypassing L1/register store path.
__global__ __launch_bounds__(256, 6)
void knn_gather_norm_bulk_kernel(const float* __restrict__ input,      // [B,N,C]
                                 const float* __restrict__ points,     // [B,N,3]
                                 const float* __restrict__ next_pts,   // [B,M,3]
                                 const int*   __restrict__ indices,    // [B,M,K]
                                 float* __restrict__ out_pts,          // [B,M,K,3]
                                 float* __restrict__ out_feat)         // [B,M,K,C]
{
    __shared__ __align__(128) float sfeat[ROWS * CC];   // 32 KB staging
    __shared__ int sidx[ROWS];

    const int tid  = threadIdx.x;
    const int wid  = tid >> 5;
    const int lane = tid & 31;

    const size_t g0 = (size_t)blockIdx.x * GROUPS;   // first bm of this CTA
    const int b = (int)(g0 / MM);                    // GROUPS | MM, so same b for all groups

    if (tid < ROWS) {
        sidx[tid] = __ldg(&indices[g0 * KK + tid]);
    }
    __syncthreads();

    // ---- feature gather into SMEM: warp wid handles rows wid, wid+8, ... ----
    #pragma unroll
    for (int r = 0; r < ROWS / 8; ++r) {
        const int rr  = r * 8 + wid;                 // 0..63  (group = rr>>5, k = rr&31)
        const int idx = sidx[rr];
        const float4* __restrict__ src =
            reinterpret_cast<const float4*>(input + ((size_t)b * NN + (size_t)idx) * CC);
        const float4 v = src[lane];
        *reinterpret_cast<float4*>(&sfeat[rr * CC + lane * 4]) = v;
    }

    // ---- pts: warp g computes group g (lane = neighbor k), direct store ----
    if (wid < GROUPS) {
        const size_t bm = g0 + wid;
        const int    k  = lane;
        const int    idx = sidx[wid * KK + k];

        const float nx = __ldg(&next_pts[bm * 3 + 0]);
        const float ny = __ldg(&next_pts[bm * 3 + 1]);
        const float nz = __ldg(&next_pts[bm * 3 + 2]);

        const float* p = points + ((size_t)b * NN + (size_t)idx) * 3;
        const float dx = __ldg(&p[0]) - nx;
        const float dy = __ldg(&p[1]) - ny;
        const float dz = __ldg(&p[2]) - nz;

        float mx = dx * dx + dy * dy + dz * dz;
        #pragma unroll
        for (int o = 16; o > 0; o >>= 1)
            mx = fmaxf(mx, __shfl_xor_sync(0xffffffffu, mx, o));

        float maxi = sqrtf(mx);
        if (maxi == 0.0f) maxi = 1.0f;
        const float inv = 1.0f / maxi;

        float* o = out_pts + (bm * KK + (size_t)k) * 3;
        o[0] = dx * inv;
        o[1] = dy * inv;
        o[2] = dz * inv;
    }

    __syncthreads();

    // ---- one bulk store: SMEM (32KB) -> contiguous GMEM feature block ----
    if (tid == 0) {
        // Order the generic-proxy STS writes before the async-proxy bulk read.
        asm volatile("fence.proxy.async.shared::cta;" ::: "memory");

        uint32_t s_addr;
        asm("{ .reg .u64 t; cvta.to.shared.u64 t, %1; cvt.u32.u64 %0, t; }"
            : "=r"(s_addr) : "l"(sfeat));

        float* dst = out_feat + g0 * KK * CC;
        asm volatile(
            "cp.async.bulk.global.shared::cta.bulk_group [%0], [%1], %2;"
            :: "l"(dst), "r"(s_addr), "n"(ROWS * CC * 4)
            : "memory");
        asm volatile("cp.async.bulk.commit_group;" ::: "memory");
        asm volatile("cp.async.bulk.wait_group 0;" ::: "memory");
    }
}

extern "C" void kernel_launch(void* const* d_in, const int* in_sizes, int n_in,
                              void* d_out, int out_size)
{
    const float* input    = (const float*)d_in[0];  // [B,N,C]
    const float* points   = (const float*)d_in[1];  // [B,N,3]
    const float* next_pts = (const float*)d_in[2];  // [B,M,3]
    const int*   indices  = (const int*)  d_in[3];  // [B,M,K]

    float* out_pts  = (float*)d_out;                         // B*M*K*3
    float* out_feat = out_pts + (size_t)BB * MM * KK * 3;    // B*M*K*C

    const int grid = (BB * MM) / GROUPS;   // 16384 CTAs
    knn_gather_norm_bulk_kernel<<<grid, 256>>>(input, points, next_pts, indices,
                                               out_pts, out_feat);
}

// round 3
// speedup vs baseline: 1.2202x; 1.2202x over previous
#include <cuda_runtime.h>
#include <cstdint>

// Problem constants (fixed by the reference)
#define BB 16
#define NN 8192
#define MM 2048
#define KK 32
#define CC 128

// out layout: [pts (B*M*K*3 floats)] ++ [features (B*M*K*C floats)]
// One CTA per (b, m). 256 threads = 8 warps.
//  - warp 0: normalized relative coords for all K=32 neighbors (lane = k)
//  - all 8 warps: copy 4 feature rows each; all 4 gather loads issued
//    back-to-back (MLP=4), then 4 streaming stores (st.global.cs).
__global__ __launch_bounds__(256, 8)
void knn_gather_norm_v3_kernel(const float* __restrict__ input,      // [B,N,C]
                               const float* __restrict__ points,     // [B,N,3]
                               const float* __restrict__ next_pts,   // [B,M,3]
                               const int*   __restrict__ indices,    // [B,M,K]
                               float* __restrict__ out_pts,          // [B,M,K,3]
                               float* __restrict__ out_feat)         // [B,M,K,C]
{
    const int bm = blockIdx.x;            // 0 .. B*M-1
    const int b  = bm / MM;

    __shared__ int sidx[KK];

    const int tid  = threadIdx.x;
    const int wid  = tid >> 5;
    const int lane = tid & 31;

    if (tid < KK) {
        sidx[tid] = __ldg(&indices[(size_t)bm * KK + tid]);
    }
    __syncthreads();

    // ---- features: warp wid owns rows {wid, wid+8, wid+16, wid+24} ----
    const float4* __restrict__ in_b =
        reinterpret_cast<const float4*>(input + (size_t)b * NN * CC);
    // each feature row = 32 float4; row r of batch b starts at in_b + idx*32

    const int i0 = sidx[wid +  0];
    const int i1 = sidx[wid +  8];
    const int i2 = sidx[wid + 16];
    const int i3 = sidx[wid + 24];

    // 4 independent gather loads in flight
    const float4 v0 = __ldg(&in_b[(size_t)i0 * (CC / 4) + lane]);
    const float4 v1 = __ldg(&in_b[(size_t)i1 * (CC / 4) + lane]);
    const float4 v2 = __ldg(&in_b[(size_t)i2 * (CC / 4) + lane]);
    const float4 v3 = __ldg(&in_b[(size_t)i3 * (CC / 4) + lane]);

    float4* __restrict__ of =
        reinterpret_cast<float4*>(out_feat + (size_t)bm * KK * CC);
    // row k of this bm starts at of + k*32

    __stcs(&of[(size_t)(wid +  0) * (CC / 4) + lane], v0);
    __stcs(&of[(size_t)(wid +  8) * (CC / 4) + lane], v1);
    __stcs(&of[(size_t)(wid + 16) * (CC / 4) + lane], v2);
    __stcs(&of[(size_t)(wid + 24) * (CC / 4) + lane], v3);

    // ---- pts: warp 0, lane = neighbor k ----
    if (wid == 0) {
        const int k   = lane;
        const int idx = sidx[k];

        const float nx = __ldg(&next_pts[(size_t)bm * 3 + 0]);
        const float ny = __ldg(&next_pts[(size_t)bm * 3 + 1]);
        const float nz = __ldg(&next_pts[(size_t)bm * 3 + 2]);

        const float* p = points + ((size_t)b * NN + (size_t)idx) * 3;
        const float dx = __ldg(&p[0]) - nx;
        const float dy = __ldg(&p[1]) - ny;
        const float dz = __ldg(&p[2]) - nz;

        float mx = dx * dx + dy * dy + dz * dz;
        #pragma unroll
        for (int o = 16; o > 0; o >>= 1)
            mx = fmaxf(mx, __shfl_xor_sync(0xffffffffu, mx, o));

        float maxi = sqrtf(mx);
        if (maxi == 0.0f) maxi = 1.0f;
        const float inv = 1.0f / maxi;

        float* o = out_pts + ((size_t)bm * KK + (size_t)k) * 3;
        o[0] = dx * inv;
        o[1] = dy * inv;
        o[2] = dz * inv;
    }
}

extern "C" void kernel_launch(void* const* d_in, const int* in_sizes, int n_in,
                              void* d_out, int out_size)
{
    const float* input    = (const float*)d_in[0];  // [B,N,C]
    const float* points   = (const float*)d_in[1];  // [B,N,3]
    const float* next_pts = (const float*)d_in[2];  // [B,M,3]
    const int*   indices  = (const int*)  d_in[3];  // [B,M,K]

    float* out_pts  = (float*)d_out;                         // B*M*K*3
    float* out_feat = out_pts + (size_t)BB * MM * KK * 3;    // B*M*K*C

    const int grid = BB * MM;   // 32768 CTAs
    knn_gather_norm_v3_kernel<<<grid, 256>>>(input, points, next_pts, indices,
                                             out_pts, out_feat);
}